// round 13
// baseline (speedup 1.0000x reference)
#include <cuda_runtime.h>
#include <math.h>

#define NMAX 100000
#define EMAX 3200000
#define ETMAX (EMAX + NMAX)
#define CAP  128        // per-node slot capacity; deg ~ Poisson(33), P(deg>=128) ~ 1e-18
#define CHK  (CAP / 8)  // 16 chunks of 8 edges
#define CHKC 8          // chunks cached in registers (64 edges; tail uses fallback path)

// ---------- scratch ----------
__device__ __align__(16) float d_h1 [NMAX * 32];
__device__ __align__(16) float d_as1[NMAX * 4];
__device__ __align__(16) float d_ad1[NMAX * 4];

__device__ __align__(16) float4 d_p2s[NMAX];   // {g0, g1, as2, unused}
__device__ __align__(16) float  d_ad2[NMAX];

// slot-based CSR by dst: fixed CAP entries per node, one-pass build
__device__ __align__(16) int  d_fill[NMAX];          // per-node cursor (zeroed in k_node1)
__device__ __align__(16) int2 d_slot[NMAX * CAP];    // {src, orig edge id}

__device__ __forceinline__ float lrelu(float v) { return v > 0.0f ? v : 0.2f * v; }

// ---------- one-pass CSR fill: 4 edges/thread, int4 edge loads ----------
__global__ void k_fill(const int* __restrict__ ei, int E, int ET) {
    int i4 = (blockIdx.x * blockDim.x + threadIdx.x) * 4;
    if (i4 >= ET) return;
    int ss[4], dd[4];
    if (i4 + 3 < E && (i4 & 3) == 0) {
        int4 s4 = *(const int4*)&ei[i4];
        int4 t4 = *(const int4*)&ei[E + i4];
        ss[0] = s4.x; ss[1] = s4.y; ss[2] = s4.z; ss[3] = s4.w;
        dd[0] = t4.x; dd[1] = t4.y; dd[2] = t4.z; dd[3] = t4.w;
    } else {
#pragma unroll
        for (int k = 0; k < 4; k++) {
            int i = i4 + k;
            if (i < ET) {
                if (i < E) { ss[k] = ei[i]; dd[k] = ei[E + i]; }
                else       { ss[k] = i - E; dd[k] = i - E; }
            } else dd[k] = -1;
        }
    }
    int pos[4];
#pragma unroll
    for (int k = 0; k < 4; k++)
        if (dd[k] >= 0) pos[k] = atomicAdd(&d_fill[dd[k]], 1);
#pragma unroll
    for (int k = 0; k < 4; k++)
        if (dd[k] >= 0 && pos[k] < CAP)
            d_slot[dd[k] * CAP + pos[k]] = make_int2(ss[k], i4 + k);
}

// ---------- layer 1: node transform (also zeroes fill counters) ----------
__global__ void k_node1(const float* __restrict__ x, const float* __restrict__ W1,
                        const float* __restrict__ asr, const float* __restrict__ adr, int N) {
    int n = blockIdx.x * blockDim.x + threadIdx.x;
    if (n >= N) return;
    d_fill[n] = 0;                       // must run before k_fill
    float x0 = x[2 * n], x1 = x[2 * n + 1];
    float h[32];
#pragma unroll
    for (int k = 0; k < 32; k++) h[k] = x0 * W1[k] + x1 * W1[32 + k];
    float4 sa, da;
    float* sap = (float*)&sa;
    float* dap = (float*)&da;
#pragma unroll
    for (int hh = 0; hh < 4; hh++) {
        float s = 0.f, d = 0.f;
#pragma unroll
        for (int c = 0; c < 8; c++) {
            s += h[hh * 8 + c] * asr[hh * 8 + c];
            d += h[hh * 8 + c] * adr[hh * 8 + c];
        }
        sap[hh] = s;
        dap[hh] = d;
    }
    ((float4*)d_as1)[n] = sa;
    ((float4*)d_ad1)[n] = da;
#pragma unroll
    for (int k = 0; k < 8; k++)
        ((float4*)d_h1)[n * 8 + k] = make_float4(h[k*4], h[k*4+1], h[k*4+2], h[k*4+3]);
}

// ---------- layer 1 conv + layer 2 node transform, fused; one warp per node ----------
// First CHKC chunks cache {px, py, ee} in registers: alpha emission is one
// unpredicated STG per chunk (each lane writes its own edge/head), aggregation
// gets px/ee via shfl. Rare tail (deg > 64) uses a reload/recompute path.
__global__ void k_conv1(const float* __restrict__ b1, const float* __restrict__ W2,
                        const float* __restrict__ asr2, const float* __restrict__ adr2,
                        float* __restrict__ alpha_out, int N) {
    int warp = (blockIdx.x * blockDim.x + threadIdx.x) >> 5;
    if (warp >= N) return;
    int n = warp;
    int lane = threadIdx.x & 31;
    int l8 = lane & 7;
    int h = lane >> 3;
    int base = n * CAP;
    int deg = min(d_fill[n], CAP);
    float ad = d_ad1[n * 4 + h];

    // phase 1: softmax denominator; cache first CHKC chunks
    float ee[CHKC];
    int   px[CHKC], py[CHKC];
    float ssum = 0.f;
#pragma unroll
    for (int c = 0; c < CHKC; c++) {
        if (c * 8 >= deg) break;            // warp-uniform (warp = node)
        int e = c * 8 + l8;
        float v = 0.f;
        int pxc = 0, pyc = -1;
        if (e < deg) {
            int2 p = d_slot[base + e];
            pxc = p.x; pyc = p.y;
            v = __expf(lrelu(d_as1[p.x * 4 + h] + ad));
        }
        px[c] = pxc; py[c] = pyc; ee[c] = v;
        ssum += v;
    }
    // rare tail chunks (deg > 64): accumulate sum only
    for (int c = CHKC; c < CHK; c++) {
        if (c * 8 >= deg) break;
        int e = c * 8 + l8;
        if (e < deg) {
            int s = d_slot[base + e].x;
            ssum += __expf(lrelu(d_as1[s * 4 + h] + ad));
        }
    }
#pragma unroll
    for (int o = 4; o >= 1; o >>= 1) ssum += __shfl_xor_sync(0xffffffffu, ssum, o, 8);
    float inv = 1.0f / (ssum + 1e-16f);

    // phase 2: aggregate unnormalized + emit alpha; scale once at the end
    float acc = 0.f;
#pragma unroll
    for (int c = 0; c < CHKC; c++) {
        if (c * 8 >= deg) break;            // warp-uniform
        // alpha: one STG, each lane (h,l8) writes its own edge's head value
        if (alpha_out && py[c] >= 0) alpha_out[py[c] * 4 + h] = ee[c] * inv;
#pragma unroll
        for (int j = 0; j < 8; j++) {
            int e = c * 8 + j;
            if (e < deg) {                  // warp-uniform
                float ev  = __shfl_sync(0xffffffffu, ee[c], j, 8);
                int   pxj = __shfl_sync(0xffffffffu, px[c], j, 8);
                acc += d_h1[pxj * 32 + lane] * ev;   // coalesced: 1 line per edge
            }
        }
    }
    // rare tail (deg > 64): reload + recompute path
    for (int c = CHKC; c < CHK; c++) {
        if (c * 8 >= deg) break;
        for (int j = 0; j < 8; j++) {
            int e = c * 8 + j;
            if (e < deg) {
                int2 p = d_slot[base + e];
                float ev = __expf(lrelu(d_as1[p.x * 4 + h] + ad));
                if (alpha_out && l8 == 0) alpha_out[p.y * 4 + h] = ev * inv;
                acc += d_h1[p.x * 32 + lane] * ev;
            }
        }
    }
    acc *= inv;

    // fused layer-2 node transform: v = elu(acc + b1), g = v @ W2, warp-reduce
    float v = acc + b1[lane];
    v = v > 0.f ? v : expm1f(v);
    float g0 = v * W2[lane * 2];
    float g1 = v * W2[lane * 2 + 1];
#pragma unroll
    for (int o = 16; o >= 1; o >>= 1) {
        g0 += __shfl_xor_sync(0xffffffffu, g0, o);
        g1 += __shfl_xor_sync(0xffffffffu, g1, o);
    }
    if (lane == 0) {
        d_p2s[n] = make_float4(g0, g1, g0 * asr2[0] + g1 * asr2[1], 0.f);
        d_ad2[n] = g0 * adr2[0] + g1 * adr2[1];
    }
}

// ---------- layer 2: single-pass softmax+aggregate (deferred normalization) ----------
// 8 lanes per dst node; p2s gathered ONCE per edge; ee cached for first CHKC
// chunks only (register pressure), rare tail recomputed in the alpha loop.
__global__ void k_conv2(float* __restrict__ out, float* __restrict__ alpha_out,
                        const float* __restrict__ b2, int N) {
    int t = blockIdx.x * blockDim.x + threadIdx.x;
    int n = t >> 3;
    if (n >= N) return;
    int l8 = t & 7;
    int base = n * CAP;
    int deg = min(d_fill[n], CAP);
    float ad = d_ad2[n];

    // warp-uniform loop bound: max degree across the 4 nodes in this warp
    int mdeg = deg;
#pragma unroll
    for (int o = 8; o <= 16; o <<= 1)
        mdeg = max(mdeg, __shfl_xor_sync(0xffffffffu, mdeg, o));

    float ee[CHKC];
    float ssum = 0.f, ax = 0.f, ay = 0.f;
#pragma unroll
    for (int c = 0; c < CHK; c++) {
        if (c * 8 >= mdeg) break;          // warp-uniform early exit
        int e = c * 8 + l8;
        float v = 0.f;
        if (e < deg) {
            float4 ps = d_p2s[d_slot[base + e].x];   // single gather per edge
            v = __expf(lrelu(ps.z + ad));
            ax += ps.x * v;
            ay += ps.y * v;
        }
        if (c < CHKC) ee[c] = v;
        ssum += v;
    }
#pragma unroll
    for (int o = 4; o >= 1; o >>= 1) {
        ssum += __shfl_xor_sync(0xffffffffu, ssum, o, 8);
        ax   += __shfl_xor_sync(0xffffffffu, ax,   o, 8);
        ay   += __shfl_xor_sync(0xffffffffu, ay,   o, 8);
    }
    float inv = 1.0f / (ssum + 1e-16f);

    if (l8 == 0) {
        out[n * 2]     = ax * inv + b2[0];
        out[n * 2 + 1] = ay * inv + b2[1];
    }

    // alpha emission: store-only loop (slot reload is an L1 hit)
    if (alpha_out) {
#pragma unroll
        for (int c = 0; c < CHK; c++) {
            if (c * 8 >= mdeg) break;
            int e = c * 8 + l8;
            if (e < deg) {
                int2 p = d_slot[base + e];
                float v = (c < CHKC) ? ee[c]
                         : __expf(lrelu(d_p2s[p.x].z + ad));   // rare tail
                alpha_out[p.y] = v * inv;
            }
        }
    }
}

// ---------- tail fill: zero any region not written elsewhere ----------
__global__ void k_tail(float* __restrict__ out, int lo, int hi) {
    int i = lo + blockIdx.x * blockDim.x + threadIdx.x;
    if (i < hi) out[i] = 0.f;
}

extern "C" void kernel_launch(void* const* d_in, const int* in_sizes, int n_in,
                              void* d_out, int out_size) {
    const float* x   = (const float*)d_in[0];
    const int*   ei  = (const int*)d_in[1];   // edge_index stored as int32 by harness
    // d_in[2] = edge_attr (ignored by reference)
    const float* W1   = (const float*)d_in[3];
    const float* as1  = (const float*)d_in[4];
    const float* ad1  = (const float*)d_in[5];
    const float* b1   = (const float*)d_in[6];
    const float* W2   = (const float*)d_in[7];
    const float* as2  = (const float*)d_in[8];
    const float* ad2  = (const float*)d_in[9];
    const float* b2   = (const float*)d_in[10];
    float* out = (float*)d_out;

    int N  = in_sizes[0] / 2;
    int E  = in_sizes[1] / 2;
    int ET = E + N;
    long long total = (long long)N * 2 + (long long)ET * 5;
    bool full = (out_size >= total);

    float* alpha1_out = full ? out + (size_t)N * 2 : nullptr;
    float* alpha2_out = full ? out + (size_t)N * 2 + (size_t)ET * 4 : nullptr;

    const int T = 256;
    int gN   = (N  + T - 1) / T;
    int gE4  = (ET + 4 * T - 1) / (4 * T);   // 4 edges per thread
    int gW   = (N * 32 + T - 1) / T;         // warp per node
    int gN8  = (N * 8  + T - 1) / T;         // 8 lanes per node

    // node1 zeroes the fill counters, so it must precede k_fill
    k_node1<<<gN, T>>>(x, W1, as1, ad1, N);
    k_fill<<<gE4, T>>>(ei, E, ET);           // one-pass slot CSR build

    // layer 1 conv + fused layer-2 node transform
    k_conv1<<<gW, T>>>(b1, W2, as2, ad2, alpha1_out, N);

    // layer 2 (single pass, writes final out rows + bias directly)
    k_conv2<<<gN8, T>>>(out, alpha2_out, b2, N);

    // zero any unwritten tail region
    int lo = full ? (int)total : N * 2;
    if (out_size > lo) {
        int cnt = out_size - lo;
        k_tail<<<(cnt + T - 1) / T, T>>>(out, lo, out_size);
    }
}

// round 14
// speedup vs baseline: 1.0880x; 1.0880x over previous
#include <cuda_runtime.h>
#include <math.h>

#define NMAX 100000
#define EMAX 3200000
#define ETMAX (EMAX + NMAX)
#define CAP  128        // per-node slot capacity; deg ~ Poisson(33), P(deg>=128) ~ 1e-18
#define CHK  (CAP / 8)  // 16 chunks of 8 edges
#define CHKC 8          // chunks cached in registers in conv2

// ---------- scratch ----------
__device__ __align__(16) float d_h1 [NMAX * 32];
__device__ __align__(16) float d_as1[NMAX * 4];
__device__ __align__(16) float d_ad1[NMAX * 4];

__device__ __align__(16) float4 d_p2s[NMAX];   // {g0, g1, as2, unused}
__device__ __align__(16) float  d_ad2[NMAX];

// slot-based CSR by dst: fixed CAP entries per node, one-pass build
__device__ __align__(16) int  d_fill[NMAX];          // per-node cursor (zeroed in k_node1)
__device__ __align__(16) int2 d_slot[NMAX * CAP];    // {src, orig edge id}

__device__ __forceinline__ float lrelu(float v) { return v > 0.0f ? v : 0.2f * v; }

// ---------- one-pass CSR fill: 4 edges/thread, int4 edge loads ----------
__global__ void k_fill(const int* __restrict__ ei, int E, int ET) {
    int i4 = (blockIdx.x * blockDim.x + threadIdx.x) * 4;
    if (i4 >= ET) return;
    int ss[4], dd[4];
    if (i4 + 3 < E && (i4 & 3) == 0) {
        int4 s4 = *(const int4*)&ei[i4];
        int4 t4 = *(const int4*)&ei[E + i4];
        ss[0] = s4.x; ss[1] = s4.y; ss[2] = s4.z; ss[3] = s4.w;
        dd[0] = t4.x; dd[1] = t4.y; dd[2] = t4.z; dd[3] = t4.w;
    } else {
#pragma unroll
        for (int k = 0; k < 4; k++) {
            int i = i4 + k;
            if (i < ET) {
                if (i < E) { ss[k] = ei[i]; dd[k] = ei[E + i]; }
                else       { ss[k] = i - E; dd[k] = i - E; }
            } else dd[k] = -1;
        }
    }
    int pos[4];
#pragma unroll
    for (int k = 0; k < 4; k++)
        if (dd[k] >= 0) pos[k] = atomicAdd(&d_fill[dd[k]], 1);
#pragma unroll
    for (int k = 0; k < 4; k++)
        if (dd[k] >= 0 && pos[k] < CAP)
            d_slot[dd[k] * CAP + pos[k]] = make_int2(ss[k], i4 + k);
}

// ---------- layer 1: node transform (also zeroes fill counters) ----------
__global__ void k_node1(const float* __restrict__ x, const float* __restrict__ W1,
                        const float* __restrict__ asr, const float* __restrict__ adr, int N) {
    int n = blockIdx.x * blockDim.x + threadIdx.x;
    if (n >= N) return;
    d_fill[n] = 0;                       // must run before k_fill
    float x0 = x[2 * n], x1 = x[2 * n + 1];
    float h[32];
#pragma unroll
    for (int k = 0; k < 32; k++) h[k] = x0 * W1[k] + x1 * W1[32 + k];
    float4 sa, da;
    float* sap = (float*)&sa;
    float* dap = (float*)&da;
#pragma unroll
    for (int hh = 0; hh < 4; hh++) {
        float s = 0.f, d = 0.f;
#pragma unroll
        for (int c = 0; c < 8; c++) {
            s += h[hh * 8 + c] * asr[hh * 8 + c];
            d += h[hh * 8 + c] * adr[hh * 8 + c];
        }
        sap[hh] = s;
        dap[hh] = d;
    }
    ((float4*)d_as1)[n] = sa;
    ((float4*)d_ad1)[n] = da;
#pragma unroll
    for (int k = 0; k < 8; k++)
        ((float4*)d_h1)[n * 8 + k] = make_float4(h[k*4], h[k*4+1], h[k*4+2], h[k*4+3]);
}

// ---------- layer 1 conv + layer 2 node transform, fused; one warp per node ----------
// R12 shape (ee-only register cache) + warp-uniform early break in phase 1.
__global__ void k_conv1(const float* __restrict__ b1, const float* __restrict__ W2,
                        const float* __restrict__ asr2, const float* __restrict__ adr2,
                        float* __restrict__ alpha_out, int N) {
    int warp = (blockIdx.x * blockDim.x + threadIdx.x) >> 5;
    if (warp >= N) return;
    int n = warp;
    int lane = threadIdx.x & 31;
    int l8 = lane & 7;
    int h = lane >> 3;
    int base = n * CAP;
    int deg = min(d_fill[n], CAP);
    float ad = d_ad1[n * 4 + h];

    // phase 1: softmax denominator; ee[c] = exp for edge c*8+l8 (head h)
    float ee[CHK];
    float ssum = 0.f;
#pragma unroll
    for (int c = 0; c < CHK; c++) {
        if (c * 8 >= deg) { ee[c] = 0.f; break; }   // warp-uniform (warp = node)
        int e = c * 8 + l8;
        float v = 0.f;
        if (e < deg) {
            int s = d_slot[base + e].x;
            v = __expf(lrelu(d_as1[s * 4 + h] + ad));
        }
        ee[c] = v;
        ssum += v;
    }
#pragma unroll
    for (int o = 4; o >= 1; o >>= 1) ssum += __shfl_xor_sync(0xffffffffu, ssum, o, 8);
    float inv = 1.0f / (ssum + 1e-16f);

    // phase 2: aggregate unnormalized, scale once at the end
    float acc = 0.f;
#pragma unroll
    for (int c = 0; c < CHK; c++) {
        if (c * 8 >= deg) break;           // warp-uniform
#pragma unroll
        for (int j = 0; j < 8; j++) {
            int e = c * 8 + j;
            if (e < deg) {                  // warp-uniform
                int2 p = d_slot[base + e];  // uniform load (L1 hit after phase 1)
                float ev = __shfl_sync(0xffffffffu, ee[c], j, 8);
                if (alpha_out && l8 == 0) alpha_out[p.y * 4 + h] = ev * inv;
                acc += d_h1[p.x * 32 + lane] * ev;   // coalesced: 1 line per edge
            }
        }
    }
    acc *= inv;

    // fused layer-2 node transform: v = elu(acc + b1), g = v @ W2, warp-reduce
    float v = acc + b1[lane];
    v = v > 0.f ? v : expm1f(v);
    float g0 = v * W2[lane * 2];
    float g1 = v * W2[lane * 2 + 1];
#pragma unroll
    for (int o = 16; o >= 1; o >>= 1) {
        g0 += __shfl_xor_sync(0xffffffffu, g0, o);
        g1 += __shfl_xor_sync(0xffffffffu, g1, o);
    }
    if (lane == 0) {
        d_p2s[n] = make_float4(g0, g1, g0 * asr2[0] + g1 * asr2[1], 0.f);
        d_ad2[n] = g0 * adr2[0] + g1 * adr2[1];
    }
}

// ---------- layer 2: single-pass softmax+aggregate (deferred normalization) ----------
// 8 lanes per dst node; p2s gathered ONCE per edge; ee cached for first CHKC
// chunks only (register pressure), rare tail recomputed in the alpha loop.
__global__ void k_conv2(float* __restrict__ out, float* __restrict__ alpha_out,
                        const float* __restrict__ b2, int N) {
    int t = blockIdx.x * blockDim.x + threadIdx.x;
    int n = t >> 3;
    if (n >= N) return;
    int l8 = t & 7;
    int base = n * CAP;
    int deg = min(d_fill[n], CAP);
    float ad = d_ad2[n];

    // warp-uniform loop bound: max degree across the 4 nodes in this warp
    int mdeg = deg;
#pragma unroll
    for (int o = 8; o <= 16; o <<= 1)
        mdeg = max(mdeg, __shfl_xor_sync(0xffffffffu, mdeg, o));

    float ee[CHKC];
    float ssum = 0.f, ax = 0.f, ay = 0.f;
#pragma unroll
    for (int c = 0; c < CHK; c++) {
        if (c * 8 >= mdeg) break;          // warp-uniform early exit
        int e = c * 8 + l8;
        float v = 0.f;
        if (e < deg) {
            float4 ps = d_p2s[d_slot[base + e].x];   // single gather per edge
            v = __expf(lrelu(ps.z + ad));
            ax += ps.x * v;
            ay += ps.y * v;
        }
        if (c < CHKC) ee[c] = v;
        ssum += v;
    }
#pragma unroll
    for (int o = 4; o >= 1; o >>= 1) {
        ssum += __shfl_xor_sync(0xffffffffu, ssum, o, 8);
        ax   += __shfl_xor_sync(0xffffffffu, ax,   o, 8);
        ay   += __shfl_xor_sync(0xffffffffu, ay,   o, 8);
    }
    float inv = 1.0f / (ssum + 1e-16f);

    if (l8 == 0) {
        out[n * 2]     = ax * inv + b2[0];
        out[n * 2 + 1] = ay * inv + b2[1];
    }

    // alpha emission: store-only loop (slot reload is an L1 hit)
    if (alpha_out) {
#pragma unroll
        for (int c = 0; c < CHK; c++) {
            if (c * 8 >= mdeg) break;
            int e = c * 8 + l8;
            if (e < deg) {
                int2 p = d_slot[base + e];
                float v = (c < CHKC) ? ee[c]
                         : __expf(lrelu(d_p2s[p.x].z + ad));   // rare tail
                alpha_out[p.y] = v * inv;
            }
        }
    }
}

// ---------- tail fill: zero any region not written elsewhere ----------
__global__ void k_tail(float* __restrict__ out, int lo, int hi) {
    int i = lo + blockIdx.x * blockDim.x + threadIdx.x;
    if (i < hi) out[i] = 0.f;
}

extern "C" void kernel_launch(void* const* d_in, const int* in_sizes, int n_in,
                              void* d_out, int out_size) {
    const float* x   = (const float*)d_in[0];
    const int*   ei  = (const int*)d_in[1];   // edge_index stored as int32 by harness
    // d_in[2] = edge_attr (ignored by reference)
    const float* W1   = (const float*)d_in[3];
    const float* as1  = (const float*)d_in[4];
    const float* ad1  = (const float*)d_in[5];
    const float* b1   = (const float*)d_in[6];
    const float* W2   = (const float*)d_in[7];
    const float* as2  = (const float*)d_in[8];
    const float* ad2  = (const float*)d_in[9];
    const float* b2   = (const float*)d_in[10];
    float* out = (float*)d_out;

    int N  = in_sizes[0] / 2;
    int E  = in_sizes[1] / 2;
    int ET = E + N;
    long long total = (long long)N * 2 + (long long)ET * 5;
    bool full = (out_size >= total);

    float* alpha1_out = full ? out + (size_t)N * 2 : nullptr;
    float* alpha2_out = full ? out + (size_t)N * 2 + (size_t)ET * 4 : nullptr;

    const int T = 256;
    int gN   = (N  + T - 1) / T;
    int gE4  = (ET + 4 * T - 1) / (4 * T);   // 4 edges per thread
    int gW   = (N * 32 + T - 1) / T;         // warp per node
    int gN8  = (N * 8  + T - 1) / T;         // 8 lanes per node

    // node1 zeroes the fill counters, so it must precede k_fill
    k_node1<<<gN, T>>>(x, W1, as1, ad1, N);
    k_fill<<<gE4, T>>>(ei, E, ET);           // one-pass slot CSR build

    // layer 1 conv + fused layer-2 node transform
    k_conv1<<<gW, T>>>(b1, W2, as2, ad2, alpha1_out, N);

    // layer 2 (single pass, writes final out rows + bias directly)
    k_conv2<<<gN8, T>>>(out, alpha2_out, b2, N);

    // zero any unwritten tail region
    int lo = full ? (int)total : N * 2;
    if (out_size > lo) {
        int cnt = out_size - lo;
        k_tail<<<(cnt + T - 1) / T, T>>>(out, lo, out_size);
    }
}

// round 15
// speedup vs baseline: 1.3664x; 1.2558x over previous
#include <cuda_runtime.h>
#include <math.h>

#define NMAX 100000
#define EMAX 3200000
#define ETMAX (EMAX + NMAX)
#define CAP  128        // per-node slot capacity; deg ~ Poisson(33), P(deg>=128) ~ 1e-18
#define CHK  (CAP / 8)  // 16 chunks of 8 edges
#define CHKC 8          // chunks cached in registers in conv2

// ---------- scratch ----------
__device__ __align__(16) float d_h1 [NMAX * 32];
__device__ __align__(16) float d_as1[NMAX * 4];
__device__ __align__(16) float d_ad1[NMAX * 4];

__device__ __align__(16) float4 d_p2s[NMAX];   // {g0, g1, as2, unused}
__device__ __align__(16) float  d_ad2[NMAX];

// slot-based CSR by dst: fixed CAP entries per node, one-pass build
__device__ __align__(16) int  d_fill[NMAX];          // per-node cursor (zeroed in k_node1)
__device__ __align__(16) int2 d_slot[NMAX * CAP];    // {src, orig edge id}

__device__ __forceinline__ float lrelu(float v) { return v > 0.0f ? v : 0.2f * v; }

// ---------- one-pass CSR fill: 4 edges/thread, int4 edge loads ----------
__global__ void k_fill(const int* __restrict__ ei, int E, int ET) {
    int i4 = (blockIdx.x * blockDim.x + threadIdx.x) * 4;
    if (i4 >= ET) return;
    int ss[4], dd[4];
    if (i4 + 3 < E && (i4 & 3) == 0) {
        int4 s4 = *(const int4*)&ei[i4];
        int4 t4 = *(const int4*)&ei[E + i4];
        ss[0] = s4.x; ss[1] = s4.y; ss[2] = s4.z; ss[3] = s4.w;
        dd[0] = t4.x; dd[1] = t4.y; dd[2] = t4.z; dd[3] = t4.w;
    } else {
#pragma unroll
        for (int k = 0; k < 4; k++) {
            int i = i4 + k;
            if (i < ET) {
                if (i < E) { ss[k] = ei[i]; dd[k] = ei[E + i]; }
                else       { ss[k] = i - E; dd[k] = i - E; }
            } else dd[k] = -1;
        }
    }
    int pos[4];
#pragma unroll
    for (int k = 0; k < 4; k++)
        if (dd[k] >= 0) pos[k] = atomicAdd(&d_fill[dd[k]], 1);
#pragma unroll
    for (int k = 0; k < 4; k++)
        if (dd[k] >= 0 && pos[k] < CAP)
            d_slot[dd[k] * CAP + pos[k]] = make_int2(ss[k], i4 + k);
}

// ---------- layer 1: node transform (also zeroes fill counters) ----------
__global__ void k_node1(const float* __restrict__ x, const float* __restrict__ W1,
                        const float* __restrict__ asr, const float* __restrict__ adr, int N) {
    int n = blockIdx.x * blockDim.x + threadIdx.x;
    if (n >= N) return;
    d_fill[n] = 0;                       // must run before k_fill
    float x0 = x[2 * n], x1 = x[2 * n + 1];
    float h[32];
#pragma unroll
    for (int k = 0; k < 32; k++) h[k] = x0 * W1[k] + x1 * W1[32 + k];
    float4 sa, da;
    float* sap = (float*)&sa;
    float* dap = (float*)&da;
#pragma unroll
    for (int hh = 0; hh < 4; hh++) {
        float s = 0.f, d = 0.f;
#pragma unroll
        for (int c = 0; c < 8; c++) {
            s += h[hh * 8 + c] * asr[hh * 8 + c];
            d += h[hh * 8 + c] * adr[hh * 8 + c];
        }
        sap[hh] = s;
        dap[hh] = d;
    }
    ((float4*)d_as1)[n] = sa;
    ((float4*)d_ad1)[n] = da;
#pragma unroll
    for (int k = 0; k < 8; k++)
        ((float4*)d_h1)[n * 8 + k] = make_float4(h[k*4], h[k*4+1], h[k*4+2], h[k*4+3]);
}

// ---------- layer 1 conv + layer 2 node transform, fused; one warp per node ----------
// phase 1: predicated full-unroll (max MLP, no break — R14 lesson)
// phase 2: 4 edges per iteration; quad q=lane>>3 owns edge e0+q, 8 lanes load
//          the full 128B h1 row as float4s. acc4 reduced via shfl_xor 8,16.
__global__ void k_conv1(const float* __restrict__ b1, const float* __restrict__ W2,
                        const float* __restrict__ asr2, const float* __restrict__ adr2,
                        float* __restrict__ alpha_out, int N) {
    int warp = (blockIdx.x * blockDim.x + threadIdx.x) >> 5;
    if (warp >= N) return;
    int n = warp;
    int lane = threadIdx.x & 31;
    int l8 = lane & 7;
    int h = lane >> 3;                 // head owned in phase 1 / alpha loop
    int q = lane >> 3;                 // quad (same value, different role)
    int base = n * CAP;
    int deg = min(d_fill[n], CAP);
    float ad = d_ad1[n * 4 + h];

    // phase 1: softmax denominator; ee[c] = exp for edge c*8+l8 (head h)
    float ee[CHK];
    float ssum = 0.f;
#pragma unroll
    for (int c = 0; c < CHK; c++) {
        int e = c * 8 + l8;
        float v = 0.f;
        if (e < deg) {
            int s = d_slot[base + e].x;
            v = __expf(lrelu(d_as1[s * 4 + h] + ad));
        }
        ee[c] = v;
        ssum += v;
    }
#pragma unroll
    for (int o = 4; o >= 1; o >>= 1) ssum += __shfl_xor_sync(0xffffffffu, ssum, o, 8);
    float inv = 1.0f / (ssum + 1e-16f);

    // alpha emission: chunked, 8 edges x 4 heads per iteration (contiguous 16B groups)
    if (alpha_out) {
#pragma unroll
        for (int c = 0; c < CHK; c++) {
            if (c * 8 >= deg) break;       // warp-uniform
            int e = c * 8 + l8;
            if (e < deg) alpha_out[d_slot[base + e].y * 4 + h] = ee[c] * inv;
        }
    }

    // phase 2: aggregation, 4 edges per iteration
    float4 acc4 = make_float4(0.f, 0.f, 0.f, 0.f);
    int hh8 = (l8 >> 1) * 8;           // owner-group base for this lane's head (l8>>1)
#pragma unroll
    for (int c = 0; c < CHK; c++) {
        if (c * 8 >= deg) break;           // warp-uniform
#pragma unroll
        for (int half = 0; half < 2; half++) {
            int e0 = c * 8 + half * 4;
            if (e0 < deg) {                // warp-uniform
                int e = e0 + q;
                // ee owner: lane hh8 + half*4 + q holds edge e, head l8>>1
                float ev = __shfl_sync(0xffffffffu, ee[c], hh8 + half * 4 + q, 32);
                if (e < deg) {
                    int src = d_slot[base + e].x;       // 4 consecutive entries: 1 line
                    float4 hv = ((const float4*)&d_h1[src * 32])[l8];
                    acc4.x += hv.x * ev;
                    acc4.y += hv.y * ev;
                    acc4.z += hv.z * ev;
                    acc4.w += hv.w * ev;
                }
            }
        }
    }
    // reduce partial sums across the 4 quads
#pragma unroll
    for (int o = 8; o <= 16; o <<= 1) {
        acc4.x += __shfl_xor_sync(0xffffffffu, acc4.x, o);
        acc4.y += __shfl_xor_sync(0xffffffffu, acc4.y, o);
        acc4.z += __shfl_xor_sync(0xffffffffu, acc4.z, o);
        acc4.w += __shfl_xor_sync(0xffffffffu, acc4.w, o);
    }
    // inv for this lane's channel head (l8>>1): held by lane (l8>>1)*8
    float invh = __shfl_sync(0xffffffffu, inv, hh8, 32);

    // fused layer-2 node transform on channels [4*l8, 4*l8+4)
    float4 bb = ((const float4*)b1)[l8];
    float4 w0 = ((const float4*)W2)[l8 * 2];       // W2 rows 4l8,4l8+1 ({c0g0,c0g1,c1g0,c1g1})
    float4 w1 = ((const float4*)W2)[l8 * 2 + 1];   // W2 rows 4l8+2,4l8+3
    float v0 = acc4.x * invh + bb.x;
    float v1 = acc4.y * invh + bb.y;
    float v2 = acc4.z * invh + bb.z;
    float v3 = acc4.w * invh + bb.w;
    v0 = v0 > 0.f ? v0 : expm1f(v0);
    v1 = v1 > 0.f ? v1 : expm1f(v1);
    v2 = v2 > 0.f ? v2 : expm1f(v2);
    v3 = v3 > 0.f ? v3 : expm1f(v3);
    float g0 = v0 * w0.x + v1 * w0.z + v2 * w1.x + v3 * w1.z;
    float g1 = v0 * w0.y + v1 * w0.w + v2 * w1.y + v3 * w1.w;
#pragma unroll
    for (int o = 4; o >= 1; o >>= 1) {            // sum channels within 8-lane group
        g0 += __shfl_xor_sync(0xffffffffu, g0, o, 8);
        g1 += __shfl_xor_sync(0xffffffffu, g1, o, 8);
    }
    if (lane == 0) {
        d_p2s[n] = make_float4(g0, g1, g0 * asr2[0] + g1 * asr2[1], 0.f);
        d_ad2[n] = g0 * adr2[0] + g1 * adr2[1];
    }
}

// ---------- layer 2: single-pass softmax+aggregate (deferred normalization) ----------
__global__ void k_conv2(float* __restrict__ out, float* __restrict__ alpha_out,
                        const float* __restrict__ b2, int N) {
    int t = blockIdx.x * blockDim.x + threadIdx.x;
    int n = t >> 3;
    if (n >= N) return;
    int l8 = t & 7;
    int base = n * CAP;
    int deg = min(d_fill[n], CAP);
    float ad = d_ad2[n];

    // warp-uniform loop bound: max degree across the 4 nodes in this warp
    int mdeg = deg;
#pragma unroll
    for (int o = 8; o <= 16; o <<= 1)
        mdeg = max(mdeg, __shfl_xor_sync(0xffffffffu, mdeg, o));

    float ee[CHKC];
    float ssum = 0.f, ax = 0.f, ay = 0.f;
#pragma unroll
    for (int c = 0; c < CHK; c++) {
        if (c * 8 >= mdeg) break;          // warp-uniform early exit
        int e = c * 8 + l8;
        float v = 0.f;
        if (e < deg) {
            float4 ps = d_p2s[d_slot[base + e].x];   // single gather per edge
            v = __expf(lrelu(ps.z + ad));
            ax += ps.x * v;
            ay += ps.y * v;
        }
        if (c < CHKC) ee[c] = v;
        ssum += v;
    }
#pragma unroll
    for (int o = 4; o >= 1; o >>= 1) {
        ssum += __shfl_xor_sync(0xffffffffu, ssum, o, 8);
        ax   += __shfl_xor_sync(0xffffffffu, ax,   o, 8);
        ay   += __shfl_xor_sync(0xffffffffu, ay,   o, 8);
    }
    float inv = 1.0f / (ssum + 1e-16f);

    if (l8 == 0) {
        out[n * 2]     = ax * inv + b2[0];
        out[n * 2 + 1] = ay * inv + b2[1];
    }

    // alpha emission: store-only loop (slot reload is an L1 hit)
    if (alpha_out) {
#pragma unroll
        for (int c = 0; c < CHK; c++) {
            if (c * 8 >= mdeg) break;
            int e = c * 8 + l8;
            if (e < deg) {
                int2 p = d_slot[base + e];
                float v = (c < CHKC) ? ee[c]
                         : __expf(lrelu(d_p2s[p.x].z + ad));   // rare tail
                alpha_out[p.y] = v * inv;
            }
        }
    }
}

// ---------- tail fill: zero any region not written elsewhere ----------
__global__ void k_tail(float* __restrict__ out, int lo, int hi) {
    int i = lo + blockIdx.x * blockDim.x + threadIdx.x;
    if (i < hi) out[i] = 0.f;
}

extern "C" void kernel_launch(void* const* d_in, const int* in_sizes, int n_in,
                              void* d_out, int out_size) {
    const float* x   = (const float*)d_in[0];
    const int*   ei  = (const int*)d_in[1];   // edge_index stored as int32 by harness
    // d_in[2] = edge_attr (ignored by reference)
    const float* W1   = (const float*)d_in[3];
    const float* as1  = (const float*)d_in[4];
    const float* ad1  = (const float*)d_in[5];
    const float* b1   = (const float*)d_in[6];
    const float* W2   = (const float*)d_in[7];
    const float* as2  = (const float*)d_in[8];
    const float* ad2  = (const float*)d_in[9];
    const float* b2   = (const float*)d_in[10];
    float* out = (float*)d_out;

    int N  = in_sizes[0] / 2;
    int E  = in_sizes[1] / 2;
    int ET = E + N;
    long long total = (long long)N * 2 + (long long)ET * 5;
    bool full = (out_size >= total);

    float* alpha1_out = full ? out + (size_t)N * 2 : nullptr;
    float* alpha2_out = full ? out + (size_t)N * 2 + (size_t)ET * 4 : nullptr;

    const int T = 256;
    int gN   = (N  + T - 1) / T;
    int gE4  = (ET + 4 * T - 1) / (4 * T);   // 4 edges per thread
    int gW   = (N * 32 + T - 1) / T;         // warp per node
    int gN8  = (N * 8  + T - 1) / T;         // 8 lanes per node

    // node1 zeroes the fill counters, so it must precede k_fill
    k_node1<<<gN, T>>>(x, W1, as1, ad1, N);
    k_fill<<<gE4, T>>>(ei, E, ET);           // one-pass slot CSR build

    // layer 1 conv + fused layer-2 node transform
    k_conv1<<<gW, T>>>(b1, W2, as2, ad2, alpha1_out, N);

    // layer 2 (single pass, writes final out rows + bias directly)
    k_conv2<<<gN8, T>>>(out, alpha2_out, b2, N);

    // zero any unwritten tail region
    int lo = full ? (int)total : N * 2;
    if (out_size > lo) {
        int cnt = out_size - lo;
        k_tail<<<(cnt + T - 1) / T, T>>>(out, lo, out_size);
    }
}